// round 10
// baseline (speedup 1.0000x reference)
#include <cuda_runtime.h>
#include <cstdint>
#include <math.h>

#define NTOK 4096
#define DM   4096
#define KE   8
#define DH   2048
#define DP   512
#define KD2  (KE*DH)   // 16384

#define BM 128
#define BN 128
#define BK 16
#define ASTR 24    // 16 + 8 pad (keeps 16B alignment, near conflict-free frag loads)
#define BSTR 132   // 128 + 4 pad (conflict-free B frag loads)
#define ASZ (BM*ASTR)   // floats per A buffer
#define BSZ (BK*BSTR)   // floats per B buffer

// ---------------- scratch (device globals; no allocation allowed) ----------
__device__ __align__(256) float g_hidp[(size_t)NTOK*KD2];   // 256 MB
__device__ __align__(256) float g_weights[NTOK*KE];
__device__ __align__(256) float g_rel[NTOK];
__device__ __align__(256) float g_q[(size_t)NTOK*DP];
__device__ __align__(256) float g_kk[(size_t)NTOK*DP];

// ---------------- helpers --------------------------------------------------
__device__ __forceinline__ uint32_t f2tf(float f){
    uint32_t u; asm("cvt.rna.tf32.f32 %0, %1;" : "=r"(u) : "f"(f)); return u;
}
__device__ __forceinline__ void mma8(float (&d)[4], const uint32_t (&a)[4], const uint32_t (&b)[2]){
    asm volatile("mma.sync.aligned.m16n8k8.row.col.f32.tf32.tf32.f32 "
        "{%0,%1,%2,%3},{%4,%5,%6,%7},{%8,%9},{%0,%1,%2,%3};"
        : "+f"(d[0]),"+f"(d[1]),"+f"(d[2]),"+f"(d[3])
        : "r"(a[0]),"r"(a[1]),"r"(a[2]),"r"(a[3]),"r"(b[0]),"r"(b[1]));
}
__device__ __forceinline__ void cpa16(uint32_t s, const float* g){
    asm volatile("cp.async.cg.shared.global [%0], [%1], 16;" :: "r"(s), "l"(g));
}
__device__ __forceinline__ float gelu_f(float x){
    return 0.5f*x*(1.0f + erff(x*0.70710678118654752f));
}

// ---------------- routing: softmax(h_mask @ Wr + br) -----------------------
// one warp per row; lane-strided over D, Wr row (8 floats) via two float4
__global__ void __launch_bounds__(256) routing_kernel(
    const float* __restrict__ hM, const float* __restrict__ Wr,
    const float* __restrict__ br)
{
    int wid = threadIdx.x >> 5, lane = threadIdx.x & 31;
    int n = blockIdx.x * 8 + wid;
    const float* hrow = hM + (size_t)n * DM;
    float a[8];
#pragma unroll
    for (int k = 0; k < 8; k++) a[k] = 0.f;
    for (int d = lane; d < DM; d += 32) {
        float x = hrow[d];
        float4 w0 = *reinterpret_cast<const float4*>(Wr + (size_t)d*8);
        float4 w1 = *reinterpret_cast<const float4*>(Wr + (size_t)d*8 + 4);
        a[0] += x*w0.x; a[1] += x*w0.y; a[2] += x*w0.z; a[3] += x*w0.w;
        a[4] += x*w1.x; a[5] += x*w1.y; a[6] += x*w1.z; a[7] += x*w1.w;
    }
#pragma unroll
    for (int k = 0; k < 8; k++)
#pragma unroll
        for (int off = 16; off > 0; off >>= 1)
            a[k] += __shfl_down_sync(0xffffffffu, a[k], off);
    if (lane == 0) {
        float l[8], m = -1e30f;
#pragma unroll
        for (int k = 0; k < 8; k++) { l[k] = a[k] + br[k]; m = fmaxf(m, l[k]); }
        float s = 0.f;
#pragma unroll
        for (int k = 0; k < 8; k++) { l[k] = expf(l[k] - m); s += l[k]; }
        float inv = 1.0f / s;
#pragma unroll
        for (int k = 0; k < 8; k++) g_weights[n*KE + k] = l[k] * inv;
    }
}

// ---------------- relevance: sigmoid(dot(q,k)/sqrt(DP)) --------------------
__global__ void __launch_bounds__(128) relevance_kernel()
{
    int n = blockIdx.x, tid = threadIdx.x;
    const float4* q4 = reinterpret_cast<const float4*>(g_q  + (size_t)n*DP);
    const float4* k4 = reinterpret_cast<const float4*>(g_kk + (size_t)n*DP);
    float4 q = q4[tid], k = k4[tid];
    float s = q.x*k.x + q.y*k.y + q.z*k.z + q.w*k.w;
#pragma unroll
    for (int off = 16; off > 0; off >>= 1) s += __shfl_down_sync(0xffffffffu, s, off);
    __shared__ float red[4];
    if ((tid & 31) == 0) red[tid >> 5] = s;
    __syncthreads();
    if (tid == 0) {
        float t = red[0] + red[1] + red[2] + red[3];
        // 1/sqrt(512)
        g_rel[n] = 1.0f / (1.0f + expf(-t * 0.04419417382415922f));
    }
}

// ---------------- generic tf32 GEMM, 128x128x16, 8 warps (64x32 warp tile) -
// MODE 1: hidp[n, z*DH+f] = w[n,z] * gelu(concat(hA,hM)[n,:] @ W1[z] + b1[z])
// MODE 2: out[n,d] = rel[n] * (hidp[n,:] @ W2flat + sum_k w[n,k]*b2[k,d])
// MODE 3: z==0: g_q = hM@Wq + bq ; z==1: g_kk = hA@Wk + bk
template<int MODE>
__global__ void __launch_bounds__(256) gemm_tf32(
    const float* __restrict__ hA, const float* __restrict__ hM,
    const float* __restrict__ W1, const float* __restrict__ b1,
    const float* __restrict__ W2, const float* __restrict__ b2,
    const float* __restrict__ Wq, const float* __restrict__ bq,
    const float* __restrict__ Wk, const float* __restrict__ bk,
    float* __restrict__ out)
{
    __shared__ float As[2*ASZ];
    __shared__ float Bs[2*BSZ];

    const int tid = threadIdx.x;
    const int m0 = blockIdx.y * BM, n0 = blockIdx.x * BN, z = blockIdx.z;

    int Kd, ldb, lda;
    const float* Bg;
    const float* Ag = nullptr;
    if (MODE == 1) { Kd = 2*DM; ldb = DH; lda = DM;  Bg = W1 + (size_t)z*(2*DM)*DH; }
    else if (MODE == 2) { Kd = KD2; ldb = DM; lda = KD2; Bg = W2; Ag = g_hidp; }
    else { Kd = DM; ldb = DP; lda = DM; Bg = z ? Wk : Wq; Ag = z ? hA : hM; }

    const uint32_t smA = (uint32_t)__cvta_generic_to_shared(As);
    const uint32_t smB = (uint32_t)__cvta_generic_to_shared(Bs);

    auto issue = [&](int t, int s) {
        const int k0 = t * BK;
        const float* At;
        if (MODE == 1) At = (k0 < DM) ? (hA + k0) : (hM + (k0 - DM));
        else           At = Ag + k0;
        uint32_t sa = smA + (uint32_t)(s*ASZ)*4u;
#pragma unroll
        for (int j = 0; j < 2; j++) {
            int row = (tid >> 2) + j*64;
            int c4  = tid & 3;
            cpa16(sa + (uint32_t)(row*ASTR + c4*4)*4u,
                  At + (size_t)(m0 + row)*lda + c4*4);
        }
        const float* Bt = Bg + (size_t)k0*ldb + n0;
        uint32_t sb = smB + (uint32_t)(s*BSZ)*4u;
#pragma unroll
        for (int j = 0; j < 2; j++) {
            int row = (tid >> 5) + j*8;
            int c4  = tid & 31;
            cpa16(sb + (uint32_t)(row*BSTR + c4*4)*4u,
                  Bt + (size_t)row*ldb + c4*4);
        }
    };

    float acc[4][4][4];
#pragma unroll
    for (int i = 0; i < 4; i++)
#pragma unroll
        for (int j = 0; j < 4; j++)
#pragma unroll
            for (int v = 0; v < 4; v++) acc[i][j][v] = 0.f;

    const int wid = tid >> 5, lane = tid & 31;
    const int wm = (wid >> 2) * 64, wn = (wid & 3) * 32;
    const int g = lane >> 2, tg = lane & 3;

    issue(0, 0);
    asm volatile("cp.async.commit_group;" ::: "memory");

    const int T = Kd / BK;
    for (int t = 0; t < T; t++) {
        if (t + 1 < T) {
            issue(t + 1, (t + 1) & 1);
            asm volatile("cp.async.commit_group;" ::: "memory");
            asm volatile("cp.async.wait_group 1;" ::: "memory");
        } else {
            asm volatile("cp.async.wait_group 0;" ::: "memory");
        }
        __syncthreads();
        const float* as = As + (t & 1) * ASZ;
        const float* bs = Bs + (t & 1) * BSZ;
#pragma unroll
        for (int kk = 0; kk < BK/8; kk++) {
            uint32_t af[4][4], bf[4][2];
#pragma unroll
            for (int mi = 0; mi < 4; mi++) {
                const float* ap = as + (wm + mi*16 + g)*ASTR + kk*8 + tg;
                af[mi][0] = f2tf(ap[0]);
                af[mi][1] = f2tf(ap[8*ASTR]);
                af[mi][2] = f2tf(ap[4]);
                af[mi][3] = f2tf(ap[8*ASTR + 4]);
            }
#pragma unroll
            for (int ni = 0; ni < 4; ni++) {
                const float* bp = bs + (kk*8 + tg)*BSTR + wn + ni*8 + g;
                bf[ni][0] = f2tf(bp[0]);
                bf[ni][1] = f2tf(bp[4*BSTR]);
            }
#pragma unroll
            for (int mi = 0; mi < 4; mi++)
#pragma unroll
                for (int ni = 0; ni < 4; ni++)
                    mma8(acc[mi][ni], af[mi], bf[ni]);
        }
        __syncthreads();
    }

    // ---------------- epilogue ----------------
#pragma unroll
    for (int mi = 0; mi < 4; mi++) {
        const int r0 = m0 + wm + mi*16 + g;
        const int r1 = r0 + 8;
        if (MODE == 1) {
            const float w0 = g_weights[r0*KE + z];
            const float w1 = g_weights[r1*KE + z];
#pragma unroll
            for (int ni = 0; ni < 4; ni++) {
                const int c0 = n0 + wn + ni*8 + tg*2;
                const float bv0 = b1[z*DH + c0];
                const float bv1 = b1[z*DH + c0 + 1];
                float* o0 = g_hidp + (size_t)r0*KD2 + z*DH + c0;
                float* o1 = g_hidp + (size_t)r1*KD2 + z*DH + c0;
                o0[0] = w0 * gelu_f(acc[mi][ni][0] + bv0);
                o0[1] = w0 * gelu_f(acc[mi][ni][1] + bv1);
                o1[0] = w1 * gelu_f(acc[mi][ni][2] + bv0);
                o1[1] = w1 * gelu_f(acc[mi][ni][3] + bv1);
            }
        } else if (MODE == 2) {
            const float rel0 = g_rel[r0], rel1 = g_rel[r1];
            float wr0[8], wr1[8];
#pragma unroll
            for (int k = 0; k < 8; k++) {
                wr0[k] = g_weights[r0*KE + k];
                wr1[k] = g_weights[r1*KE + k];
            }
#pragma unroll
            for (int ni = 0; ni < 4; ni++) {
                const int c0 = n0 + wn + ni*8 + tg*2;
                float s00 = 0.f, s01 = 0.f, s10 = 0.f, s11 = 0.f;
#pragma unroll
                for (int k = 0; k < 8; k++) {
                    const float bc0 = b2[(size_t)k*DM + c0];
                    const float bc1 = b2[(size_t)k*DM + c0 + 1];
                    s00 += wr0[k]*bc0; s01 += wr0[k]*bc1;
                    s10 += wr1[k]*bc0; s11 += wr1[k]*bc1;
                }
                out[(size_t)r0*DM + c0    ] = rel0 * (acc[mi][ni][0] + s00);
                out[(size_t)r0*DM + c0 + 1] = rel0 * (acc[mi][ni][1] + s01);
                out[(size_t)r1*DM + c0    ] = rel1 * (acc[mi][ni][2] + s10);
                out[(size_t)r1*DM + c0 + 1] = rel1 * (acc[mi][ni][3] + s11);
            }
        } else {
            const float* bias = z ? bk : bq;
            float* op = z ? g_kk : g_q;
#pragma unroll
            for (int ni = 0; ni < 4; ni++) {
                const int c0 = n0 + wn + ni*8 + tg*2;
                const float bv0 = bias[c0], bv1 = bias[c0 + 1];
                op[(size_t)r0*DP + c0    ] = acc[mi][ni][0] + bv0;
                op[(size_t)r0*DP + c0 + 1] = acc[mi][ni][1] + bv1;
                op[(size_t)r1*DP + c0    ] = acc[mi][ni][2] + bv0;
                op[(size_t)r1*DP + c0 + 1] = acc[mi][ni][3] + bv1;
            }
        }
    }
}

// ---------------- launch ---------------------------------------------------
extern "C" void kernel_launch(void* const* d_in, const int* in_sizes, int n_in,
                              void* d_out, int out_size)
{
    (void)in_sizes; (void)n_in; (void)out_size;
    const float* hA = (const float*)d_in[0];
    const float* hM = (const float*)d_in[1];
    const float* Wr = (const float*)d_in[2];
    const float* br = (const float*)d_in[3];
    const float* W1 = (const float*)d_in[4];
    const float* b1 = (const float*)d_in[5];
    const float* W2 = (const float*)d_in[6];
    const float* b2 = (const float*)d_in[7];
    const float* Wq = (const float*)d_in[8];
    const float* bq = (const float*)d_in[9];
    const float* Wk = (const float*)d_in[10];
    const float* bk = (const float*)d_in[11];
    float* out = (float*)d_out;

    // 1) routing softmax weights
    routing_kernel<<<NTOK/8, 256>>>(hM, Wr, br);
    // 2) q/k projections (z-batched)
    gemm_tf32<3><<<dim3(DP/BN, NTOK/BM, 2), 256>>>(hA,hM,W1,b1,W2,b2,Wq,bq,Wk,bk,out);
    // 3) relevance gate
    relevance_kernel<<<NTOK, 128>>>();
    // 4) expert up-proj + gelu, routing weight folded into hidp
    gemm_tf32<1><<<dim3(DH/BN, NTOK/BM, KE), 256>>>(hA,hM,W1,b1,W2,b2,Wq,bq,Wk,bk,out);
    // 5) single fused down-proj over Kd=16384 (= mixture), gated epilogue
    gemm_tf32<2><<<dim3(DM/BN, NTOK/BM, 1), 256>>>(hA,hM,W1,b1,W2,b2,Wq,bq,Wk,bk,out);
}

// round 12
// speedup vs baseline: 1.1556x; 1.1556x over previous
#include <cuda_runtime.h>
#include <cstdint>
#include <math.h>

#define NTOK 4096
#define DM   4096
#define KE   8
#define DH   2048
#define DP   512
#define KD2  (KE*DH)   // 16384
#define D2   (2*DM)    // 8192

#define BM 128
#define BN 128
#define BK 16
#define ASTR 24    // 16 + 8 pad; LDS.64 frag loads conflict-free
#define BSTR 132   // 128 + 4 pad
#define ASZ (BM*ASTR)
#define BSZ (BK*BSTR)

// ---------------- scratch (device globals; no allocation allowed) ----------
__device__ __align__(256) float g_hidp[(size_t)NTOK*KD2];        // 256 MB (tf32-rounded)
__device__ __align__(256) float g_cond[(size_t)NTOK*D2];         // 128 MB (tf32-rounded [hA|hM])
__device__ __align__(256) float g_W1t[(size_t)KE*D2*DH];         // 512 MB
__device__ __align__(256) float g_W2t[(size_t)KE*DH*DM];         // 256 MB
__device__ __align__(256) float g_Wqt[(size_t)DM*DP];            // 8 MB
__device__ __align__(256) float g_Wkt[(size_t)DM*DP];            // 8 MB
__device__ __align__(256) float g_weights[NTOK*KE];
__device__ __align__(256) float g_rel[NTOK];
__device__ __align__(256) float g_q[(size_t)NTOK*DP];
__device__ __align__(256) float g_kk[(size_t)NTOK*DP];

// ---------------- helpers --------------------------------------------------
__device__ __forceinline__ uint32_t f2tf(float f){
    uint32_t u; asm("cvt.rna.tf32.f32 %0, %1;" : "=r"(u) : "f"(f)); return u;
}
__device__ __forceinline__ float rtf(float f){ return __uint_as_float(f2tf(f)); }
__device__ __forceinline__ void mma8(float (&d)[4], const uint32_t (&a)[4], const uint32_t (&b)[2]){
    asm volatile("mma.sync.aligned.m16n8k8.row.col.f32.tf32.tf32.f32 "
        "{%0,%1,%2,%3},{%4,%5,%6,%7},{%8,%9},{%0,%1,%2,%3};"
        : "+f"(d[0]),"+f"(d[1]),"+f"(d[2]),"+f"(d[3])
        : "r"(a[0]),"r"(a[1]),"r"(a[2]),"r"(a[3]),"r"(b[0]),"r"(b[1]));
}
__device__ __forceinline__ void cpa16(uint32_t s, const float* g){
    asm volatile("cp.async.cg.shared.global [%0], [%1], 16;" :: "r"(s), "l"(g));
}
__device__ __forceinline__ float gelu_f(float x){
    return 0.5f*x*(1.0f + erff(x*0.70710678118654752f));
}

// ---------------- prepass: tf32-round buffers ------------------------------
__global__ void __launch_bounds__(256) round_flat(
    const float4* __restrict__ in, float4* __restrict__ out, long n4)
{
    long i = (long)blockIdx.x*blockDim.x + threadIdx.x;
    long s = (long)gridDim.x*blockDim.x;
    for (; i < n4; i += s) {
        float4 v = in[i];
        v.x = rtf(v.x); v.y = rtf(v.y); v.z = rtf(v.z); v.w = rtf(v.w);
        out[i] = v;
    }
}
// g_cond[n, 0:DM) = round(hA[n]); g_cond[n, DM:2DM) = round(hM[n])
__global__ void __launch_bounds__(256) round_cond(
    const float4* __restrict__ hA, const float4* __restrict__ hM)
{
    const long R = DM/4;           // float4s per half-row
    long i = (long)blockIdx.x*blockDim.x + threadIdx.x;
    long s = (long)gridDim.x*blockDim.x;
    float4* c4 = reinterpret_cast<float4*>(g_cond);
    for (; i < (long)NTOK*R; i += s) {
        long n = i / R, c = i - n*R;
        float4 a = hA[i], m = hM[i];
        a.x=rtf(a.x); a.y=rtf(a.y); a.z=rtf(a.z); a.w=rtf(a.w);
        m.x=rtf(m.x); m.y=rtf(m.y); m.z=rtf(m.z); m.w=rtf(m.w);
        c4[n*(2*R) + c]     = a;
        c4[n*(2*R) + R + c] = m;
    }
}

// ---------------- routing: softmax(h_mask @ Wr + br) -----------------------
__global__ void __launch_bounds__(256) routing_kernel(
    const float* __restrict__ hM, const float* __restrict__ Wr,
    const float* __restrict__ br)
{
    int wid = threadIdx.x >> 5, lane = threadIdx.x & 31;
    int n = blockIdx.x * 8 + wid;
    const float* hrow = hM + (size_t)n * DM;
    float a[8];
#pragma unroll
    for (int k = 0; k < 8; k++) a[k] = 0.f;
    for (int d = lane; d < DM; d += 32) {
        float x = hrow[d];
        float4 w0 = *reinterpret_cast<const float4*>(Wr + (size_t)d*8);
        float4 w1 = *reinterpret_cast<const float4*>(Wr + (size_t)d*8 + 4);
        a[0] += x*w0.x; a[1] += x*w0.y; a[2] += x*w0.z; a[3] += x*w0.w;
        a[4] += x*w1.x; a[5] += x*w1.y; a[6] += x*w1.z; a[7] += x*w1.w;
    }
#pragma unroll
    for (int k = 0; k < 8; k++)
#pragma unroll
        for (int off = 16; off > 0; off >>= 1)
            a[k] += __shfl_down_sync(0xffffffffu, a[k], off);
    if (lane == 0) {
        float l[8], m = -1e30f;
#pragma unroll
        for (int k = 0; k < 8; k++) { l[k] = a[k] + br[k]; m = fmaxf(m, l[k]); }
        float s = 0.f;
#pragma unroll
        for (int k = 0; k < 8; k++) { l[k] = expf(l[k] - m); s += l[k]; }
        float inv = 1.0f / s;
#pragma unroll
        for (int k = 0; k < 8; k++) g_weights[n*KE + k] = l[k] * inv;
    }
}

// ---------------- relevance: sigmoid(dot(q,k)/sqrt(DP)) --------------------
__global__ void __launch_bounds__(128) relevance_kernel()
{
    int n = blockIdx.x, tid = threadIdx.x;
    const float4* q4 = reinterpret_cast<const float4*>(g_q  + (size_t)n*DP);
    const float4* k4 = reinterpret_cast<const float4*>(g_kk + (size_t)n*DP);
    float4 q = q4[tid], k = k4[tid];
    float s = q.x*k.x + q.y*k.y + q.z*k.z + q.w*k.w;
#pragma unroll
    for (int off = 16; off > 0; off >>= 1) s += __shfl_down_sync(0xffffffffu, s, off);
    __shared__ float red[4];
    if ((tid & 31) == 0) red[tid >> 5] = s;
    __syncthreads();
    if (tid == 0) {
        float t = red[0] + red[1] + red[2] + red[3];
        g_rel[n] = 1.0f / (1.0f + expf(-t * 0.04419417382415922f)); // 1/sqrt(512)
    }
}

// ---------------- generic tf32 GEMM, 128x128x16, 8 warps (64x32 warp tile) -
// Operands pre-rounded to tf32 in global memory: NO cvt in the inner loop.
// K-permutation trick: HW col t <-> orig col 2t, HW col t+4 <-> orig col 2t+1
// (applied to both A cols and B rows) -> A frag pairs are LDS.64.
// MODE 1: hidp[n, z*DH+f] = round(w[n,z] * gelu(cond @ W1[z] + b1[z]))
// MODE 2: out[n,d] = rel[n] * (hidp[n,:] @ W2flat + sum_k w[n,k]*b2[k,d])
// MODE 3: z==0: g_q = hM@Wq + bq ; z==1: g_kk = hA@Wk + bk
template<int MODE>
__global__ void __launch_bounds__(256) gemm_tf32(
    const float* __restrict__ b1, const float* __restrict__ b2,
    const float* __restrict__ bq, const float* __restrict__ bk,
    float* __restrict__ out)
{
    __shared__ float As[2*ASZ];
    __shared__ float Bs[2*BSZ];

    const int tid = threadIdx.x;
    const int m0 = blockIdx.y * BM, n0 = blockIdx.x * BN, z = blockIdx.z;

    int Kd, ldb, lda;
    const float* Bg;
    const float* Ag;
    if (MODE == 1)      { Kd = D2;  ldb = DH; lda = D2;  Bg = g_W1t + (size_t)z*D2*DH; Ag = g_cond; }
    else if (MODE == 2) { Kd = KD2; ldb = DM; lda = KD2; Bg = g_W2t; Ag = g_hidp; }
    else                { Kd = DM;  ldb = DP; lda = D2;  Bg = z ? g_Wkt : g_Wqt;
                          Ag = z ? g_cond : (g_cond + DM); }  // z=0: hM half, z=1: hA half

    const uint32_t smA = (uint32_t)__cvta_generic_to_shared(As);
    const uint32_t smB = (uint32_t)__cvta_generic_to_shared(Bs);

    auto issue = [&](int t, int s) {
        const int k0 = t * BK;
        const float* At = Ag + k0;
        uint32_t sa = smA + (uint32_t)(s*ASZ)*4u;
#pragma unroll
        for (int j = 0; j < 2; j++) {
            int row = (tid >> 2) + j*64;
            int c4  = tid & 3;
            cpa16(sa + (uint32_t)(row*ASTR + c4*4)*4u,
                  At + (size_t)(m0 + row)*lda + c4*4);
        }
        const float* Bt = Bg + (size_t)k0*ldb + n0;
        uint32_t sb = smB + (uint32_t)(s*BSZ)*4u;
#pragma unroll
        for (int j = 0; j < 2; j++) {
            int row = (tid >> 5) + j*8;
            int c4  = tid & 31;
            cpa16(sb + (uint32_t)(row*BSTR + c4*4)*4u,
                  Bt + (size_t)row*ldb + c4*4);
        }
    };

    float acc[4][4][4];
#pragma unroll
    for (int i = 0; i < 4; i++)
#pragma unroll
        for (int j = 0; j < 4; j++)
#pragma unroll
            for (int v = 0; v < 4; v++) acc[i][j][v] = 0.f;

    const int wid = tid >> 5, lane = tid & 31;
    const int wm = (wid >> 2) * 64, wn = (wid & 3) * 32;
    const int g = lane >> 2, tg = lane & 3;

    issue(0, 0);
    asm volatile("cp.async.commit_group;" ::: "memory");

    const int T = Kd / BK;
    for (int t = 0; t < T; t++) {
        if (t + 1 < T) {
            issue(t + 1, (t + 1) & 1);
            asm volatile("cp.async.commit_group;" ::: "memory");
            asm volatile("cp.async.wait_group 1;" ::: "memory");
        } else {
            asm volatile("cp.async.wait_group 0;" ::: "memory");
        }
        __syncthreads();
        const float* as = As + (t & 1) * ASZ;
        const float* bs = Bs + (t & 1) * BSZ;
#pragma unroll
        for (int kk = 0; kk < BK/8; kk++) {
            uint32_t af[4][4], bf[4][2];
#pragma unroll
            for (int mi = 0; mi < 4; mi++) {
                // lane reads orig cols (2tg, 2tg+1) == HW cols (tg, tg+4): LDS.64 pairs
                const float* ap = as + (wm + mi*16 + g)*ASTR + kk*8 + 2*tg;
                uint2 lo = *reinterpret_cast<const uint2*>(ap);
                uint2 hi = *reinterpret_cast<const uint2*>(ap + 8*ASTR);
                af[mi][0] = lo.x;  // a0: row g,   HW col tg   (orig 2tg)
                af[mi][1] = hi.x;  // a1: row g+8, HW col tg
                af[mi][2] = lo.y;  // a2: row g,   HW col tg+4 (orig 2tg+1)
                af[mi][3] = hi.y;  // a3: row g+8, HW col tg+4
            }
#pragma unroll
            for (int ni = 0; ni < 4; ni++) {
                const float* bp = bs + (kk*8 + 2*tg)*BSTR + wn + ni*8 + g;
                bf[ni][0] = __float_as_uint(bp[0]);      // HW row tg   (orig 2tg)
                bf[ni][1] = __float_as_uint(bp[BSTR]);   // HW row tg+4 (orig 2tg+1)
            }
#pragma unroll
            for (int mi = 0; mi < 4; mi++)
#pragma unroll
                for (int ni = 0; ni < 4; ni++)
                    mma8(acc[mi][ni], af[mi], bf[ni]);
        }
        __syncthreads();
    }

    // ---------------- epilogue ----------------
#pragma unroll
    for (int mi = 0; mi < 4; mi++) {
        const int r0 = m0 + wm + mi*16 + g;
        const int r1 = r0 + 8;
        if (MODE == 1) {
            const float w0 = g_weights[r0*KE + z];
            const float w1 = g_weights[r1*KE + z];
#pragma unroll
            for (int ni = 0; ni < 4; ni++) {
                const int c0 = n0 + wn + ni*8 + tg*2;
                const float bv0 = b1[z*DH + c0];
                const float bv1 = b1[z*DH + c0 + 1];
                float* o0 = g_hidp + (size_t)r0*KD2 + z*DH + c0;
                float* o1 = g_hidp + (size_t)r1*KD2 + z*DH + c0;
                o0[0] = rtf(w0 * gelu_f(acc[mi][ni][0] + bv0));
                o0[1] = rtf(w0 * gelu_f(acc[mi][ni][1] + bv1));
                o1[0] = rtf(w1 * gelu_f(acc[mi][ni][2] + bv0));
                o1[1] = rtf(w1 * gelu_f(acc[mi][ni][3] + bv1));
            }
        } else if (MODE == 2) {
            const float rel0 = g_rel[r0], rel1 = g_rel[r1];
            float wr0[8], wr1[8];
#pragma unroll
            for (int k = 0; k < 8; k++) {
                wr0[k] = g_weights[r0*KE + k];
                wr1[k] = g_weights[r1*KE + k];
            }
#pragma unroll
            for (int ni = 0; ni < 4; ni++) {
                const int c0 = n0 + wn + ni*8 + tg*2;
                float s00 = 0.f, s01 = 0.f, s10 = 0.f, s11 = 0.f;
#pragma unroll
                for (int k = 0; k < 8; k++) {
                    const float bc0 = b2[(size_t)k*DM + c0];
                    const float bc1 = b2[(size_t)k*DM + c0 + 1];
                    s00 += wr0[k]*bc0; s01 += wr0[k]*bc1;
                    s10 += wr1[k]*bc0; s11 += wr1[k]*bc1;
                }
                out[(size_t)r0*DM + c0    ] = rel0 * (acc[mi][ni][0] + s00);
                out[(size_t)r0*DM + c0 + 1] = rel0 * (acc[mi][ni][1] + s01);
                out[(size_t)r1*DM + c0    ] = rel1 * (acc[mi][ni][2] + s10);
                out[(size_t)r1*DM + c0 + 1] = rel1 * (acc[mi][ni][3] + s11);
            }
        } else {
            const float* bias = z ? bk : bq;
            float* op = z ? g_kk : g_q;
#pragma unroll
            for (int ni = 0; ni < 4; ni++) {
                const int c0 = n0 + wn + ni*8 + tg*2;
                const float bv0 = bias[c0], bv1 = bias[c0 + 1];
                op[(size_t)r0*DP + c0    ] = acc[mi][ni][0] + bv0;
                op[(size_t)r0*DP + c0 + 1] = acc[mi][ni][1] + bv1;
                op[(size_t)r1*DP + c0    ] = acc[mi][ni][2] + bv0;
                op[(size_t)r1*DP + c0 + 1] = acc[mi][ni][3] + bv1;
            }
        }
    }
}

// ---------------- launch ---------------------------------------------------
extern "C" void kernel_launch(void* const* d_in, const int* in_sizes, int n_in,
                              void* d_out, int out_size)
{
    (void)in_sizes; (void)n_in; (void)out_size;
    const float* hA = (const float*)d_in[0];
    const float* hM = (const float*)d_in[1];
    const float* Wr = (const float*)d_in[2];
    const float* br = (const float*)d_in[3];
    const float* W1 = (const float*)d_in[4];
    const float* b1 = (const float*)d_in[5];
    const float* W2 = (const float*)d_in[6];
    const float* b2 = (const float*)d_in[7];
    const float* Wq = (const float*)d_in[8];
    const float* bq = (const float*)d_in[9];
    const float* Wk = (const float*)d_in[10];
    const float* bk = (const float*)d_in[11];
    float* out = (float*)d_out;

    float *dW1t, *dW2t, *dWqt, *dWkt;
    cudaGetSymbolAddress((void**)&dW1t, g_W1t);
    cudaGetSymbolAddress((void**)&dW2t, g_W2t);
    cudaGetSymbolAddress((void**)&dWqt, g_Wqt);
    cudaGetSymbolAddress((void**)&dWkt, g_Wkt);

    // 0) tf32 pre-rounding prepass (removes all cvt from GEMM inner loops)
    round_flat<<<8192, 256>>>((const float4*)W1, (float4*)dW1t, (long)KE*D2*DH/4);
    round_flat<<<8192, 256>>>((const float4*)W2, (float4*)dW2t, (long)KE*DH*DM/4);
    round_flat<<<2048, 256>>>((const float4*)Wq, (float4*)dWqt, (long)DM*DP/4);
    round_flat<<<2048, 256>>>((const float4*)Wk, (float4*)dWkt, (long)DM*DP/4);
    round_cond<<<8192, 256>>>((const float4*)hA, (const float4*)hM);

    // 1) routing softmax weights
    routing_kernel<<<NTOK/8, 256>>>(hM, Wr, br);
    // 2) q/k projections (z-batched)
    gemm_tf32<3><<<dim3(DP/BN, NTOK/BM, 2), 256>>>(b1, b2, bq, bk, out);
    // 3) relevance gate
    relevance_kernel<<<NTOK, 128>>>();
    // 4) expert up-proj + gelu, routing weight folded into hidp
    gemm_tf32<1><<<dim3(DH/BN, NTOK/BM, KE), 256>>>(b1, b2, bq, bk, out);
    // 5) single fused down-proj over Kd=16384 (= mixture), gated epilogue
    gemm_tf32<2><<<dim3(DM/BN, NTOK/BM, 1), 256>>>(b1, b2, bq, bk, out);
}

// round 17
// speedup vs baseline: 1.4522x; 1.2566x over previous
#include <cuda_runtime.h>
#include <cstdint>
#include <math.h>

#define NTOK 4096
#define DM   4096
#define KE   8
#define DH   2048
#define DP   512
#define KD2  (KE*DH)   // 16384
#define D2   (2*DM)    // 8192

#define BM 128
#define BN 128
#define BK 32
#define STR 40         // 32 + 8 pad floats; LDS.64 frags conflict-free, 16B-aligned rows
#define TSZ (128*STR)  // floats per (A or B) buffer = 5120
#define SMEM_TOT (4*TSZ*4)   // 2 buffers x (A+B) = 81920 bytes

// ---------------- scratch (device globals; no allocation allowed) ----------
__device__ __align__(256) float g_hidp[(size_t)NTOK*KD2];   // 256 MB (tf32-rounded)
__device__ __align__(256) float g_cond[(size_t)NTOK*D2];    // 128 MB (tf32-rounded [hA|hM])
__device__ __align__(256) float g_W1t[(size_t)KE*DH*D2];    // 512 MB [z][n][k]
__device__ __align__(256) float g_W2t[(size_t)DM*KD2];      // 256 MB [n][k]
__device__ __align__(256) float g_Wqt[(size_t)DP*DM];       // 8 MB   [n][k]
__device__ __align__(256) float g_Wkt[(size_t)DP*DM];       // 8 MB
__device__ __align__(256) float g_weights[NTOK*KE];
__device__ __align__(256) float g_rel[NTOK];
__device__ __align__(256) float g_q[(size_t)NTOK*DP];
__device__ __align__(256) float g_kk[(size_t)NTOK*DP];

// ---------------- helpers --------------------------------------------------
__device__ __forceinline__ uint32_t f2tf(float f){
    uint32_t u; asm("cvt.rna.tf32.f32 %0, %1;" : "=r"(u) : "f"(f)); return u;
}
__device__ __forceinline__ float rtf(float f){ return __uint_as_float(f2tf(f)); }
__device__ __forceinline__ void mma8(float (&d)[4], const uint32_t (&a)[4], const uint32_t (&b)[2]){
    asm volatile("mma.sync.aligned.m16n8k8.row.col.f32.tf32.tf32.f32 "
        "{%0,%1,%2,%3},{%4,%5,%6,%7},{%8,%9},{%0,%1,%2,%3};"
        : "+f"(d[0]),"+f"(d[1]),"+f"(d[2]),"+f"(d[3])
        : "r"(a[0]),"r"(a[1]),"r"(a[2]),"r"(a[3]),"r"(b[0]),"r"(b[1]));
}
__device__ __forceinline__ void cpa16(uint32_t s, const float* g){
    asm volatile("cp.async.cg.shared.global [%0], [%1], 16;" :: "r"(s), "l"(g));
}
__device__ __forceinline__ float gelu_f(float x){
    return 0.5f*x*(1.0f + erff(x*0.70710678118654752f));
}

// ---------------- prepasses ------------------------------------------------
// out[z][c][r] = rtf(in[z][r][c]); in [nz][R][C]
__global__ void __launch_bounds__(256) transpose_round(
    const float* __restrict__ in, float* __restrict__ out, int R, int C)
{
    __shared__ float tile[32][33];
    const size_t zo = (size_t)blockIdx.z * (size_t)R * C;
    const int c0 = blockIdx.x*32, r0 = blockIdx.y*32;
    const int tx = threadIdx.x & 31, ty = threadIdx.x >> 5;
#pragma unroll
    for (int j = 0; j < 4; j++)
        tile[ty + j*8][tx] = rtf(in[zo + (size_t)(r0 + ty + j*8)*C + c0 + tx]);
    __syncthreads();
#pragma unroll
    for (int j = 0; j < 4; j++)
        out[zo + (size_t)(c0 + ty + j*8)*R + r0 + tx] = tile[tx][ty + j*8];
}
// g_cond[n, 0:DM) = round(hA[n]); g_cond[n, DM:2DM) = round(hM[n])
__global__ void __launch_bounds__(256) round_cond(
    const float4* __restrict__ hA, const float4* __restrict__ hM)
{
    const long R = DM/4;
    long i = (long)blockIdx.x*blockDim.x + threadIdx.x;
    long s = (long)gridDim.x*blockDim.x;
    float4* c4 = reinterpret_cast<float4*>(g_cond);
    for (; i < (long)NTOK*R; i += s) {
        long n = i / R, c = i - n*R;
        float4 a = hA[i], m = hM[i];
        a.x=rtf(a.x); a.y=rtf(a.y); a.z=rtf(a.z); a.w=rtf(a.w);
        m.x=rtf(m.x); m.y=rtf(m.y); m.z=rtf(m.z); m.w=rtf(m.w);
        c4[n*(2*R) + c] = a; c4[n*(2*R) + R + c] = m;
    }
}

// ---------------- routing / relevance --------------------------------------
__global__ void __launch_bounds__(256) routing_kernel(
    const float* __restrict__ hM, const float* __restrict__ Wr,
    const float* __restrict__ br)
{
    int wid = threadIdx.x >> 5, lane = threadIdx.x & 31;
    int n = blockIdx.x * 8 + wid;
    const float* hrow = hM + (size_t)n * DM;
    float a[8];
#pragma unroll
    for (int k = 0; k < 8; k++) a[k] = 0.f;
    for (int d = lane; d < DM; d += 32) {
        float x = hrow[d];
        float4 w0 = *reinterpret_cast<const float4*>(Wr + (size_t)d*8);
        float4 w1 = *reinterpret_cast<const float4*>(Wr + (size_t)d*8 + 4);
        a[0]+=x*w0.x; a[1]+=x*w0.y; a[2]+=x*w0.z; a[3]+=x*w0.w;
        a[4]+=x*w1.x; a[5]+=x*w1.y; a[6]+=x*w1.z; a[7]+=x*w1.w;
    }
#pragma unroll
    for (int k = 0; k < 8; k++)
#pragma unroll
        for (int off = 16; off > 0; off >>= 1)
            a[k] += __shfl_down_sync(0xffffffffu, a[k], off);
    if (lane == 0) {
        float l[8], m = -1e30f;
#pragma unroll
        for (int k = 0; k < 8; k++) { l[k] = a[k] + br[k]; m = fmaxf(m, l[k]); }
        float s = 0.f;
#pragma unroll
        for (int k = 0; k < 8; k++) { l[k] = expf(l[k] - m); s += l[k]; }
        float inv = 1.0f / s;
#pragma unroll
        for (int k = 0; k < 8; k++) g_weights[n*KE + k] = l[k] * inv;
    }
}
__global__ void __launch_bounds__(128) relevance_kernel()
{
    int n = blockIdx.x, tid = threadIdx.x;
    const float4* q4 = reinterpret_cast<const float4*>(g_q  + (size_t)n*DP);
    const float4* k4 = reinterpret_cast<const float4*>(g_kk + (size_t)n*DP);
    float4 q = q4[tid], k = k4[tid];
    float s = q.x*k.x + q.y*k.y + q.z*k.z + q.w*k.w;
#pragma unroll
    for (int off = 16; off > 0; off >>= 1) s += __shfl_down_sync(0xffffffffu, s, off);
    __shared__ float red[4];
    if ((tid & 31) == 0) red[tid >> 5] = s;
    __syncthreads();
    if (tid == 0) {
        float t = red[0] + red[1] + red[2] + red[3];
        g_rel[n] = 1.0f / (1.0f + expf(-t * 0.04419417382415922f)); // 1/sqrt(512)
    }
}

// ---------------- tf32 GEMM, 128x128x32, 8 warps (64x32 warp tile) ---------
// A [m][k], B [n][k] (both k-major, pre-rounded). K-permutation: HW col t <->
// orig 2t, t+4 <-> 2t+1 on both operands -> A AND B frags are LDS.64.
// MODE 1: hidp = rtf(w * gelu(cond@W1^T + b1))   MODE 2: out = rel*(hidp@W2^T + mix b2)
// MODE 3: z0: q = hM@Wq + bq ; z1: kk = hA@Wk + bk
template<int MODE>
__global__ void __launch_bounds__(256,2) gemm_tf32(
    const float* __restrict__ b1, const float* __restrict__ b2,
    const float* __restrict__ bq, const float* __restrict__ bk,
    float* __restrict__ out)
{
    extern __shared__ float smf[];
    float* As = smf;                // 2 x TSZ
    float* Bs = smf + 2*TSZ;        // 2 x TSZ

    const int tid = threadIdx.x;
    const int m0 = blockIdx.y * BM, n0 = blockIdx.x * BN, z = blockIdx.z;

    int Kd, lda;
    const float *Ag, *Bg;
    if (MODE == 1)      { Kd = D2;  lda = D2;
                          Ag = g_cond; Bg = g_W1t + (size_t)z*DH*D2 + (size_t)n0*D2; }
    else if (MODE == 2) { Kd = KD2; lda = KD2;
                          Ag = g_hidp; Bg = g_W2t + (size_t)n0*KD2; }
    else                { Kd = DM;  lda = D2;
                          Ag = z ? g_cond : (g_cond + DM);  // z=0: hM half, z=1: hA half
                          Bg = (z ? g_Wkt : g_Wqt) + (size_t)n0*DM; }
    const int ldb = Kd;

    const uint32_t smA = (uint32_t)__cvta_generic_to_shared(As);
    const uint32_t smB = (uint32_t)__cvta_generic_to_shared(Bs);

    auto issue = [&](int t, int s) {
        const int k0 = t * BK;
        const uint32_t sa = smA + (uint32_t)(s*TSZ)*4u;
        const uint32_t sb = smB + (uint32_t)(s*TSZ)*4u;
#pragma unroll
        for (int i = 0; i < 4; i++) {
            const int idx = tid + i*256;
            const int row = idx >> 3, c = idx & 7;
            cpa16(sa + (uint32_t)(row*STR*4 + c*16),
                  Ag + (size_t)(m0 + row)*lda + k0 + c*4);
            cpa16(sb + (uint32_t)(row*STR*4 + c*16),
                  Bg + (size_t)row*ldb + k0 + c*4);
        }
        asm volatile("cp.async.commit_group;" ::: "memory");
    };

    float acc[4][4][4];
#pragma unroll
    for (int i = 0; i < 4; i++)
#pragma unroll
        for (int j = 0; j < 4; j++)
#pragma unroll
            for (int v = 0; v < 4; v++) acc[i][j][v] = 0.f;

    const int wid = tid >> 5, lane = tid & 31;
    const int wm = (wid >> 2) * 64, wn = (wid & 3) * 32;
    const int g = lane >> 2, tg = lane & 3;

    issue(0, 0);

    const int T = Kd / BK;
    for (int t = 0; t < T; t++) {
        if (t + 1 < T) {
            issue(t + 1, (t + 1) & 1);
            asm volatile("cp.async.wait_group 1;" ::: "memory");
        } else {
            asm volatile("cp.async.wait_group 0;" ::: "memory");
        }
        __syncthreads();
        const float* as = As + (t & 1) * TSZ;
        const float* bs = Bs + (t & 1) * TSZ;
#pragma unroll
        for (int kk = 0; kk < BK/8; kk++) {
            uint32_t af[4][4], bf[4][2];
#pragma unroll
            for (int mi = 0; mi < 4; mi++) {
                const float* ap = as + (wm + mi*16 + g)*STR + kk*8 + 2*tg;
                uint2 lo = *reinterpret_cast<const uint2*>(ap);
                uint2 hi = *reinterpret_cast<const uint2*>(ap + 8*STR);
                af[mi][0] = lo.x;  af[mi][1] = hi.x;
                af[mi][2] = lo.y;  af[mi][3] = hi.y;
            }
#pragma unroll
            for (int ni = 0; ni < 4; ni++) {
                const float* bp = bs + (wn + ni*8 + g)*STR + kk*8 + 2*tg;
                uint2 bb = *reinterpret_cast<const uint2*>(bp);
                bf[ni][0] = bb.x;  bf[ni][1] = bb.y;
            }
#pragma unroll
            for (int mi = 0; mi < 4; mi++)
#pragma unroll
                for (int ni = 0; ni < 4; ni++)
                    mma8(acc[mi][ni], af[mi], bf[ni]);
        }
        __syncthreads();
    }

    // ---------------- epilogue ----------------
#pragma unroll
    for (int mi = 0; mi < 4; mi++) {
        const int r0 = m0 + wm + mi*16 + g;
        const int r1 = r0 + 8;
        if (MODE == 1) {
            const float w0 = g_weights[r0*KE + z];
            const float w1 = g_weights[r1*KE + z];
#pragma unroll
            for (int ni = 0; ni < 4; ni++) {
                const int c0 = n0 + wn + ni*8 + tg*2;
                const float bv0 = b1[z*DH + c0];
                const float bv1 = b1[z*DH + c0 + 1];
                float* o0 = g_hidp + (size_t)r0*KD2 + z*DH + c0;
                float* o1 = g_hidp + (size_t)r1*KD2 + z*DH + c0;
                o0[0] = rtf(w0 * gelu_f(acc[mi][ni][0] + bv0));
                o0[1] = rtf(w0 * gelu_f(acc[mi][ni][1] + bv1));
                o1[0] = rtf(w1 * gelu_f(acc[mi][ni][2] + bv0));
                o1[1] = rtf(w1 * gelu_f(acc[mi][ni][3] + bv1));
            }
        } else if (MODE == 2) {
            const float rel0 = g_rel[r0], rel1 = g_rel[r1];
            float wr0[8], wr1[8];
#pragma unroll
            for (int k = 0; k < 8; k++) {
                wr0[k] = g_weights[r0*KE + k];
                wr1[k] = g_weights[r1*KE + k];
            }
#pragma unroll
            for (int ni = 0; ni < 4; ni++) {
                const int c0 = n0 + wn + ni*8 + tg*2;
                float s00 = 0.f, s01 = 0.f, s10 = 0.f, s11 = 0.f;
#pragma unroll
                for (int k = 0; k < 8; k++) {
                    const float bc0 = b2[(size_t)k*DM + c0];
                    const float bc1 = b2[(size_t)k*DM + c0 + 1];
                    s00 += wr0[k]*bc0; s01 += wr0[k]*bc1;
                    s10 += wr1[k]*bc0; s11 += wr1[k]*bc1;
                }
                out[(size_t)r0*DM + c0    ] = rel0 * (acc[mi][ni][0] + s00);
                out[(size_t)r0*DM + c0 + 1] = rel0 * (acc[mi][ni][1] + s01);
                out[(size_t)r1*DM + c0    ] = rel1 * (acc[mi][ni][2] + s10);
                out[(size_t)r1*DM + c0 + 1] = rel1 * (acc[mi][ni][3] + s11);
            }
        } else {
            const float* bias = z ? bk : bq;
            float* op = z ? g_kk : g_q;
#pragma unroll
            for (int ni = 0; ni < 4; ni++) {
                const int c0 = n0 + wn + ni*8 + tg*2;
                const float bv0 = bias[c0], bv1 = bias[c0 + 1];
                op[(size_t)r0*DP + c0    ] = acc[mi][ni][0] + bv0;
                op[(size_t)r0*DP + c0 + 1] = acc[mi][ni][1] + bv1;
                op[(size_t)r1*DP + c0    ] = acc[mi][ni][2] + bv0;
                op[(size_t)r1*DP + c0 + 1] = acc[mi][ni][3] + bv1;
            }
        }
    }
}

// ---------------- launch ---------------------------------------------------
extern "C" void kernel_launch(void* const* d_in, const int* in_sizes, int n_in,
                              void* d_out, int out_size)
{
    (void)in_sizes; (void)n_in; (void)out_size;
    const float* hA = (const float*)d_in[0];
    const float* hM = (const float*)d_in[1];
    const float* Wr = (const float*)d_in[2];
    const float* br = (const float*)d_in[3];
    const float* W1 = (const float*)d_in[4];
    const float* b1 = (const float*)d_in[5];
    const float* W2 = (const float*)d_in[6];
    const float* b2 = (const float*)d_in[7];
    const float* Wq = (const float*)d_in[8];
    const float* bq = (const float*)d_in[9];
    const float* Wk = (const float*)d_in[10];
    const float* bk = (const float*)d_in[11];
    float* out = (float*)d_out;

    float *dW1t, *dW2t, *dWqt, *dWkt;
    cudaGetSymbolAddress((void**)&dW1t, g_W1t);
    cudaGetSymbolAddress((void**)&dW2t, g_W2t);
    cudaGetSymbolAddress((void**)&dWqt, g_Wqt);
    cudaGetSymbolAddress((void**)&dWkt, g_Wkt);

    cudaFuncSetAttribute(gemm_tf32<1>, cudaFuncAttributeMaxDynamicSharedMemorySize, SMEM_TOT);
    cudaFuncSetAttribute(gemm_tf32<2>, cudaFuncAttributeMaxDynamicSharedMemorySize, SMEM_TOT);
    cudaFuncSetAttribute(gemm_tf32<3>, cudaFuncAttributeMaxDynamicSharedMemorySize, SMEM_TOT);

    // 0) prepass: transpose+round weights to [n][k]; round activations
    transpose_round<<<dim3(DH/32,  D2/32,  KE), 256>>>(W1, dW1t, D2,  DH);
    transpose_round<<<dim3(DM/32,  KD2/32, 1 ), 256>>>(W2, dW2t, KD2, DM);
    transpose_round<<<dim3(DP/32,  DM/32,  1 ), 256>>>(Wq, dWqt, DM,  DP);
    transpose_round<<<dim3(DP/32,  DM/32,  1 ), 256>>>(Wk, dWkt, DM,  DP);
    round_cond<<<8192, 256>>>((const float4*)hA, (const float4*)hM);

    // 1) routing softmax weights
    routing_kernel<<<NTOK/8, 256>>>(hM, Wr, br);
    // 2) q/k projections (z-batched)
    gemm_tf32<3><<<dim3(DP/BN, NTOK/BM, 2),  256, SMEM_TOT>>>(b1, b2, bq, bk, out);
    // 3) relevance gate
    relevance_kernel<<<NTOK, 128>>>();
    // 4) expert up-proj + gelu, routing weight folded into hidp
    gemm_tf32<1><<<dim3(DH/BN, NTOK/BM, KE), 256, SMEM_TOT>>>(b1, b2, bq, bk, out);
    // 5) single fused down-proj over Kd=16384 (= mixture), gated epilogue
    gemm_tf32<2><<<dim3(DM/BN, NTOK/BM, 1),  256, SMEM_TOT>>>(b1, b2, bq, bk, out);
}